// round 7
// baseline (speedup 1.0000x reference)
#include <cuda_runtime.h>

#define S_DIM 256
#define H_DIM 256
#define W_DIM 256
#define F_DIM 6
#define B_DIM 4096
#define NQ (B_DIM * 4)          // 16384 queries, q = b*4 + t*2 + es
#define NBIN 16384              // sort key = (x<<6) | (y>>2): 4-cell (96B) bins
#define S_STRIDE (H_DIM * W_DIM * F_DIM)

__device__ int   g_bin[NBIN];   // static zero-init; k_scan re-zeroes each call
__device__ int   g_off[NBIN];
__device__ int   g_keys[NQ];
__device__ int   g_perm[NQ];
__device__ float g_qv[NQ];

__device__ __forceinline__ int query_key(const float* __restrict__ phi, int q) {
    const int b  = q >> 2;
    const int t  = (q >> 1) & 1;
    const int es = q & 1;
    const float* p = phi + b * 20 + t * 10;
    const int x = (int)p[6 + 2 * es];
    const int y = (int)p[7 + 2 * es];
    return (x << 6) | (y >> 2);
}

// ---------- phase A: keys + global histogram (grid-wide) ----------
__global__ __launch_bounds__(1024)
void k_hist(const float* __restrict__ phi) {
    const int q = blockIdx.x * 1024 + threadIdx.x;
    const int key = query_key(phi, q);
    g_keys[q] = key;
    atomicAdd(&g_bin[key], 1);
}

// ---------- phase B: exclusive scan of 16384 bins, one block; re-zero g_bin ----------
__global__ __launch_bounds__(1024)
void k_scan() {
    __shared__ int wsum[32];
    const int tid  = threadIdx.x;
    const int lane = tid & 31;
    const int wid  = tid >> 5;
    const int base = tid * 16;

    int c[16];
    int tsum = 0;
#pragma unroll
    for (int u = 0; u < 16; u++) { c[u] = g_bin[base + u]; tsum += c[u]; }

    int incl = tsum;
#pragma unroll
    for (int off = 1; off < 32; off <<= 1) {
        const int n = __shfl_up_sync(0xffffffffu, incl, off);
        if (lane >= off) incl += n;
    }
    if (lane == 31) wsum[wid] = incl;
    __syncthreads();
    if (wid == 0) {
        const int v = wsum[lane];
        int iv = v;
#pragma unroll
        for (int off = 1; off < 32; off <<= 1) {
            const int n = __shfl_up_sync(0xffffffffu, iv, off);
            if (lane >= off) iv += n;
        }
        wsum[lane] = iv - v;   // exclusive warp offsets
    }
    __syncthreads();

    int run = incl - tsum + wsum[wid];
#pragma unroll
    for (int u = 0; u < 16; u++) {
        g_off[base + u] = run;
        run += c[u];
        g_bin[base + u] = 0;   // restore invariant for the next replay
    }
}

// ---------- phase C: scatter (grid-wide; intra-bin order arbitrary) ----------
__global__ __launch_bounds__(1024)
void k_scatter() {
    const int q = blockIdx.x * 1024 + threadIdx.x;
    const int pos = atomicAdd(&g_off[g_keys[q]], 1);
    g_perm[pos] = q;
}

// ---------- main gather: warp = 4 consecutive sorted queries x 8 s-lanes ----------
// After the fine sort, a warp's 4 queries usually share one 128B line, so the
// per-instruction warp coalescer emits ~1 line request per plane step.
__global__ __launch_bounds__(128, 8)
void k_main(const float* __restrict__ phi,
            const float* __restrict__ w_lin,
            const float* __restrict__ succ) {
    const int warp = threadIdx.x >> 5;
    const int lane = threadIdx.x & 31;
    const int w    = blockIdx.x * 4 + warp;

    const int ql = lane >> 3;
    const int k  = lane & 7;

    const int q  = g_perm[w * 4 + ql];
    const int b  = q >> 2;
    const int t  = (q >> 1) & 1;
    const int es = q & 1;

    const float w0 = __ldg(w_lin + 0);
    const float w1 = __ldg(w_lin + 1);
    const float w2 = __ldg(w_lin + 2);
    const float w3 = __ldg(w_lin + 3);
    const float w4 = __ldg(w_lin + 4);
    const float w5 = __ldg(w_lin + 5);

    const float* p = phi + b * 20 + t * 10;
    const int x = (int)p[6 + 2 * es];
    const int y = (int)p[7 + 2 * es];

    const float* base = succ + ((size_t)(x * W_DIM + y)) * F_DIM
                             + (size_t)(k * 32) * S_STRIDE;

    float m = -3.0e38f, se = 0.0f, sev = 0.0f;

    for (int j0 = 0; j0 < 32; j0 += 4) {
#pragma unroll
        for (int u = 0; u < 4; u++) {
            const float* ptr = base + (size_t)(j0 + u) * S_STRIDE;
            const float2 a = __ldg((const float2*)(ptr + 0));
            const float2 c = __ldg((const float2*)(ptr + 2));
            const float2 d = __ldg((const float2*)(ptr + 4));
            const float v = fmaf(a.x, w0, fmaf(a.y, w1,
                            fmaf(c.x, w2, fmaf(c.y, w3,
                            fmaf(d.x, w4, d.y * w5)))));
            const float mo = m;
            m = fmaxf(m, v);
            const float corr = __expf(mo - m);
            const float e    = __expf(v - m);
            se  = fmaf(se,  corr, e);
            sev = fmaf(sev, corr, e * v);
        }
        __syncthreads();   // pace warps: keep the block's line reuse tight
    }

#pragma unroll
    for (int off = 4; off > 0; off >>= 1) {
        const float m2   = __shfl_xor_sync(0xffffffffu, m,   off);
        const float se2  = __shfl_xor_sync(0xffffffffu, se,  off);
        const float sev2 = __shfl_xor_sync(0xffffffffu, sev, off);
        const float mm = fmaxf(m, m2);
        const float c1 = __expf(m  - mm);
        const float c2 = __expf(m2 - mm);
        se  = fmaf(se,  c1, se2  * c2);
        sev = fmaf(sev, c1, sev2 * c2);
        m = mm;
    }

    if (k == 0) g_qv[q] = sev / se;
}

// ---------- final combine ----------
__global__ void k_final(const float* __restrict__ phi,
                        const float* __restrict__ w_lin,
                        float* __restrict__ out) {
    const int b = blockIdx.x * blockDim.x + threadIdx.x;
    if (b >= B_DIM) return;

    const float w0 = __ldg(w_lin + 0);
    const float w1 = __ldg(w_lin + 1);
    const float w2 = __ldg(w_lin + 2);
    const float w3 = __ldg(w_lin + 3);
    const float w4 = __ldg(w_lin + 4);
    const float w5 = __ldg(w_lin + 5);

    const float* p0 = phi + b * 20;
    const float* p1 = p0 + 10;
    const float pr0 = fmaf(p0[0], w0, fmaf(p0[1], w1, fmaf(p0[2], w2,
                      fmaf(p0[3], w3, fmaf(p0[4], w4, p0[5] * w5)))));
    const float pr1 = fmaf(p1[0], w0, fmaf(p1[1], w1, fmaf(p1[2], w2,
                      fmaf(p1[3], w3, fmaf(p1[4], w4, p1[5] * w5)))));

    const float vss0 = g_qv[b * 4 + 0];
    const float ves0 = g_qv[b * 4 + 1];
    const float vss1 = g_qv[b * 4 + 2];
    const float ves1 = g_qv[b * 4 + 3];

    const float left_der  = pr0 + (ves0 - vss0);
    const float right_der = pr1 + (ves1 - vss1);
    const float d = left_der - right_der;

    float2 r;
    r.x = 1.0f / (1.0f + expf(-d));
    r.y = 1.0f / (1.0f + expf(d));
    reinterpret_cast<float2*>(out)[b] = r;
}

extern "C" void kernel_launch(void* const* d_in, const int* in_sizes, int n_in,
                              void* d_out, int out_size) {
    const float* phi   = (const float*)d_in[0];  // (B, 2, 10)
    const float* w_lin = (const float*)d_in[1];  // (1, 6)
    const float* succ  = (const float*)d_in[2];  // (S, H, W, F)
    float* out = (float*)d_out;                  // (B, 2, 1)

    k_hist<<<NQ / 1024, 1024>>>(phi);
    k_scan<<<1, 1024>>>();
    k_scatter<<<NQ / 1024, 1024>>>();
    k_main<<<NQ / 16, 128>>>(phi, w_lin, succ);
    k_final<<<B_DIM / 128, 128>>>(phi, w_lin, out);
}

// round 8
// speedup vs baseline: 1.1340x; 1.1340x over previous
#include <cuda_runtime.h>

#define S_DIM 256
#define H_DIM 256
#define W_DIM 256
#define F_DIM 6
#define B_DIM 4096
#define NQ (B_DIM * 4)          // 16384 queries, q = b*4 + t*2 + es
#define NBIN 8192               // sort key = (x<<5) | (y>>3): 8-cell (192B) bins
#define S_STRIDE (H_DIM * W_DIM * F_DIM)

__device__ int   g_bin[NBIN];   // static zero-init; k_scan re-zeroes each call
__device__ int   g_off[NBIN];
__device__ int   g_keys[NQ];
__device__ int   g_perm[NQ];
__device__ float g_qv[NQ];

__device__ __forceinline__ int query_key(const float* __restrict__ phi, int q) {
    const int b  = q >> 2;
    const int t  = (q >> 1) & 1;
    const int es = q & 1;
    const float* p = phi + b * 20 + t * 10;
    const int x = (int)p[6 + 2 * es];
    const int y = (int)p[7 + 2 * es];
    return (x << 5) | (y >> 3);
}

// ---------- phase A: keys + global histogram (16 blocks) ----------
__global__ __launch_bounds__(1024)
void k_hist(const float* __restrict__ phi) {
    const int q = blockIdx.x * 1024 + threadIdx.x;
    const int key = query_key(phi, q);
    g_keys[q] = key;
    atomicAdd(&g_bin[key], 1);
}

// ---------- phase B: exclusive scan of 8192 bins (1 block); re-zero g_bin ----------
__global__ __launch_bounds__(1024)
void k_scan() {
    __shared__ int wsum[32];
    const int tid  = threadIdx.x;
    const int lane = tid & 31;
    const int wid  = tid >> 5;
    const int base = tid * 8;

    int c[8];
    int tsum = 0;
#pragma unroll
    for (int u = 0; u < 8; u++) { c[u] = g_bin[base + u]; tsum += c[u]; }

    int incl = tsum;
#pragma unroll
    for (int off = 1; off < 32; off <<= 1) {
        const int n = __shfl_up_sync(0xffffffffu, incl, off);
        if (lane >= off) incl += n;
    }
    if (lane == 31) wsum[wid] = incl;
    __syncthreads();
    if (wid == 0) {
        const int v = wsum[lane];
        int iv = v;
#pragma unroll
        for (int off = 1; off < 32; off <<= 1) {
            const int n = __shfl_up_sync(0xffffffffu, iv, off);
            if (lane >= off) iv += n;
        }
        wsum[lane] = iv - v;   // exclusive warp offsets
    }
    __syncthreads();

    int run = incl - tsum + wsum[wid];
#pragma unroll
    for (int u = 0; u < 8; u++) {
        g_off[base + u] = run;
        run += c[u];
        g_bin[base + u] = 0;   // restore invariant for the next graph replay
    }
}

// ---------- phase C: scatter (16 blocks; intra-bin order arbitrary) ----------
__global__ __launch_bounds__(1024)
void k_scatter() {
    const int q = blockIdx.x * 1024 + threadIdx.x;
    const int pos = atomicAdd(&g_off[g_keys[q]], 1);
    g_perm[pos] = q;
}

// ---------- main gather: warp = 4 consecutive sorted queries x 8 s-lanes ----------
// Sorted same-line queries sit in lanes {k, k+8, k+16, k+24} of one load
// instruction -> the warp coalescer merges them into ~1 line request per plane.
// 64-thread blocks / grid 2048 -> ~14 blocks/SM, no block syncs: latency-bound
// throughput comes from occupancy + 2 independent online-softmax chains.
__global__ __launch_bounds__(64, 16)
void k_main(const float* __restrict__ phi,
            const float* __restrict__ w_lin,
            const float* __restrict__ succ) {
    const int warp = threadIdx.x >> 5;
    const int lane = threadIdx.x & 31;
    const int w    = blockIdx.x * 2 + warp;

    const int ql = lane >> 3;
    const int k  = lane & 7;

    const int q  = g_perm[w * 4 + ql];
    const int b  = q >> 2;
    const int t  = (q >> 1) & 1;
    const int es = q & 1;

    const float w0 = __ldg(w_lin + 0);
    const float w1 = __ldg(w_lin + 1);
    const float w2 = __ldg(w_lin + 2);
    const float w3 = __ldg(w_lin + 3);
    const float w4 = __ldg(w_lin + 4);
    const float w5 = __ldg(w_lin + 5);

    const float* p = phi + b * 20 + t * 10;
    const int x = (int)p[6 + 2 * es];
    const int y = (int)p[7 + 2 * es];

    const float* base = succ + ((size_t)(x * W_DIM + y)) * F_DIM
                             + (size_t)(k * 32) * S_STRIDE;

    // two independent online-softmax chains (even/odd planes)
    float mA = -3.0e38f, seA = 0.0f, sevA = 0.0f;
    float mB = -3.0e38f, seB = 0.0f, sevB = 0.0f;

#pragma unroll
    for (int j = 0; j < 32; j += 2) {
        const float* pa = base + (size_t)j * S_STRIDE;
        const float* pb = pa + S_STRIDE;
        const float2 a0 = __ldg((const float2*)(pa + 0));
        const float2 a1 = __ldg((const float2*)(pa + 2));
        const float2 a2 = __ldg((const float2*)(pa + 4));
        const float2 b0 = __ldg((const float2*)(pb + 0));
        const float2 b1 = __ldg((const float2*)(pb + 2));
        const float2 b2 = __ldg((const float2*)(pb + 4));

        const float vA = fmaf(a0.x, w0, fmaf(a0.y, w1,
                         fmaf(a1.x, w2, fmaf(a1.y, w3,
                         fmaf(a2.x, w4, a2.y * w5)))));
        const float vB = fmaf(b0.x, w0, fmaf(b0.y, w1,
                         fmaf(b1.x, w2, fmaf(b1.y, w3,
                         fmaf(b2.x, w4, b2.y * w5)))));

        const float moA = mA;
        mA = fmaxf(mA, vA);
        const float cA = __expf(moA - mA);
        const float eA = __expf(vA - mA);
        seA  = fmaf(seA,  cA, eA);
        sevA = fmaf(sevA, cA, eA * vA);

        const float moB = mB;
        mB = fmaxf(mB, vB);
        const float cB = __expf(moB - mB);
        const float eB = __expf(vB - mB);
        seB  = fmaf(seB,  cB, eB);
        sevB = fmaf(sevB, cB, eB * vB);
    }

    // merge the two chains
    float m = fmaxf(mA, mB);
    {
        const float cA = __expf(mA - m);
        const float cB = __expf(mB - m);
        seA  = fmaf(seA,  cA, seB  * cB);
        sevA = fmaf(sevA, cA, sevB * cB);
    }
    float se = seA, sev = sevA;

    // merge (m, se, sev) across the 8-lane group
#pragma unroll
    for (int off = 4; off > 0; off >>= 1) {
        const float m2   = __shfl_xor_sync(0xffffffffu, m,   off);
        const float se2  = __shfl_xor_sync(0xffffffffu, se,  off);
        const float sev2 = __shfl_xor_sync(0xffffffffu, sev, off);
        const float mm = fmaxf(m, m2);
        const float c1 = __expf(m  - mm);
        const float c2 = __expf(m2 - mm);
        se  = fmaf(se,  c1, se2  * c2);
        sev = fmaf(sev, c1, sev2 * c2);
        m = mm;
    }

    if (k == 0) g_qv[q] = sev / se;
}

// ---------- final combine ----------
__global__ void k_final(const float* __restrict__ phi,
                        const float* __restrict__ w_lin,
                        float* __restrict__ out) {
    const int b = blockIdx.x * blockDim.x + threadIdx.x;
    if (b >= B_DIM) return;

    const float w0 = __ldg(w_lin + 0);
    const float w1 = __ldg(w_lin + 1);
    const float w2 = __ldg(w_lin + 2);
    const float w3 = __ldg(w_lin + 3);
    const float w4 = __ldg(w_lin + 4);
    const float w5 = __ldg(w_lin + 5);

    const float* p0 = phi + b * 20;
    const float* p1 = p0 + 10;
    const float pr0 = fmaf(p0[0], w0, fmaf(p0[1], w1, fmaf(p0[2], w2,
                      fmaf(p0[3], w3, fmaf(p0[4], w4, p0[5] * w5)))));
    const float pr1 = fmaf(p1[0], w0, fmaf(p1[1], w1, fmaf(p1[2], w2,
                      fmaf(p1[3], w3, fmaf(p1[4], w4, p1[5] * w5)))));

    const float vss0 = g_qv[b * 4 + 0];
    const float ves0 = g_qv[b * 4 + 1];
    const float vss1 = g_qv[b * 4 + 2];
    const float ves1 = g_qv[b * 4 + 3];

    const float left_der  = pr0 + (ves0 - vss0);
    const float right_der = pr1 + (ves1 - vss1);
    const float d = left_der - right_der;

    float2 r;
    r.x = 1.0f / (1.0f + expf(-d));
    r.y = 1.0f / (1.0f + expf(d));
    reinterpret_cast<float2*>(out)[b] = r;
}

extern "C" void kernel_launch(void* const* d_in, const int* in_sizes, int n_in,
                              void* d_out, int out_size) {
    const float* phi   = (const float*)d_in[0];  // (B, 2, 10)
    const float* w_lin = (const float*)d_in[1];  // (1, 6)
    const float* succ  = (const float*)d_in[2];  // (S, H, W, F)
    float* out = (float*)d_out;                  // (B, 2, 1)

    k_hist<<<NQ / 1024, 1024>>>(phi);
    k_scan<<<1, 1024>>>();
    k_scatter<<<NQ / 1024, 1024>>>();
    k_main<<<NQ / 8, 64>>>(phi, w_lin, succ);
    k_final<<<B_DIM / 128, 128>>>(phi, w_lin, out);
}

// round 9
// speedup vs baseline: 1.1609x; 1.0237x over previous
#include <cuda_runtime.h>

#define S_DIM 256
#define H_DIM 256
#define W_DIM 256
#define F_DIM 6
#define B_DIM 4096
#define NQ (B_DIM * 4)          // 16384 queries, q = b*4 + t*2 + es
#define NBIN 8192               // sort key = (x<<5) | (y>>3)
#define S_STRIDE (H_DIM * W_DIM * F_DIM)

__device__ int   g_bin[NBIN];   // static zero-init; k_scan re-zeroes each call
__device__ int   g_off[NBIN];
__device__ int   g_keys[NQ];
__device__ int   g_perm[NQ];
__device__ float g_qv[NQ];
__device__ int   g_done[B_DIM]; // static zero-init; reset by the 4th arriver

// L2-only load, sector-granular fill (no 128B promotion like __ldg/.nc)
__device__ __forceinline__ float2 ldcg2(const float* p) {
    float2 r;
    asm("ld.global.cg.v2.f32 {%0,%1}, [%2];"
        : "=f"(r.x), "=f"(r.y) : "l"(p));
    return r;
}

__device__ __forceinline__ int query_key(const float* __restrict__ phi, int q) {
    const int b  = q >> 2;
    const int t  = (q >> 1) & 1;
    const int es = q & 1;
    const float* p = phi + b * 20 + t * 10;
    const int x = (int)p[6 + 2 * es];
    const int y = (int)p[7 + 2 * es];
    return (x << 5) | (y >> 3);
}

// ---------- phase A: keys + global histogram ----------
__global__ __launch_bounds__(1024)
void k_hist(const float* __restrict__ phi) {
    const int q = blockIdx.x * 1024 + threadIdx.x;
    const int key = query_key(phi, q);
    g_keys[q] = key;
    atomicAdd(&g_bin[key], 1);
}

// ---------- phase B: exclusive scan of 8192 bins (1 block); re-zero g_bin ----------
__global__ __launch_bounds__(1024)
void k_scan() {
    __shared__ int wsum[32];
    const int tid  = threadIdx.x;
    const int lane = tid & 31;
    const int wid  = tid >> 5;
    const int base = tid * 8;

    int c[8];
    int tsum = 0;
#pragma unroll
    for (int u = 0; u < 8; u++) { c[u] = g_bin[base + u]; tsum += c[u]; }

    int incl = tsum;
#pragma unroll
    for (int off = 1; off < 32; off <<= 1) {
        const int n = __shfl_up_sync(0xffffffffu, incl, off);
        if (lane >= off) incl += n;
    }
    if (lane == 31) wsum[wid] = incl;
    __syncthreads();
    if (wid == 0) {
        const int v = wsum[lane];
        int iv = v;
#pragma unroll
        for (int off = 1; off < 32; off <<= 1) {
            const int n = __shfl_up_sync(0xffffffffu, iv, off);
            if (lane >= off) iv += n;
        }
        wsum[lane] = iv - v;
    }
    __syncthreads();

    int run = incl - tsum + wsum[wid];
#pragma unroll
    for (int u = 0; u < 8; u++) {
        g_off[base + u] = run;
        run += c[u];
        g_bin[base + u] = 0;
    }
}

// ---------- phase C: scatter ----------
__global__ __launch_bounds__(1024)
void k_scatter() {
    const int q = blockIdx.x * 1024 + threadIdx.x;
    const int pos = atomicAdd(&g_off[g_keys[q]], 1);
    g_perm[pos] = q;
}

// ---------- main gather (round-7 shape) + fused per-b combine ----------
__global__ __launch_bounds__(128, 8)
void k_main(const float* __restrict__ phi,
            const float* __restrict__ w_lin,
            const float* __restrict__ succ,
            float* __restrict__ out) {
    const int warp = threadIdx.x >> 5;
    const int lane = threadIdx.x & 31;
    const int w    = blockIdx.x * 4 + warp;

    const int ql = lane >> 3;
    const int k  = lane & 7;

    const int q  = g_perm[w * 4 + ql];
    const int b  = q >> 2;
    const int t  = (q >> 1) & 1;
    const int es = q & 1;

    const float w0 = __ldg(w_lin + 0);
    const float w1 = __ldg(w_lin + 1);
    const float w2 = __ldg(w_lin + 2);
    const float w3 = __ldg(w_lin + 3);
    const float w4 = __ldg(w_lin + 4);
    const float w5 = __ldg(w_lin + 5);

    const float* p = phi + b * 20 + t * 10;
    const int x = (int)p[6 + 2 * es];
    const int y = (int)p[7 + 2 * es];

    const float* base = succ + ((size_t)(x * W_DIM + y)) * F_DIM
                             + (size_t)(k * 32) * S_STRIDE;

    float m = -3.0e38f, se = 0.0f, sev = 0.0f;

    for (int j0 = 0; j0 < 32; j0 += 4) {
#pragma unroll
        for (int u = 0; u < 4; u++) {
            const float* ptr = base + (size_t)(j0 + u) * S_STRIDE;
            const float2 a = ldcg2(ptr + 0);
            const float2 c = ldcg2(ptr + 2);
            const float2 d = ldcg2(ptr + 4);
            const float v = fmaf(a.x, w0, fmaf(a.y, w1,
                            fmaf(c.x, w2, fmaf(c.y, w3,
                            fmaf(d.x, w4, d.y * w5)))));
            const float mo = m;
            m = fmaxf(m, v);
            const float corr = __expf(mo - m);
            const float e    = __expf(v - m);
            se  = fmaf(se,  corr, e);
            sev = fmaf(sev, corr, e * v);
        }
        __syncthreads();   // pace warps: keep block-level reuse tight
    }

    // merge (m, se, sev) across the 8-lane group
#pragma unroll
    for (int off = 4; off > 0; off >>= 1) {
        const float m2   = __shfl_xor_sync(0xffffffffu, m,   off);
        const float se2  = __shfl_xor_sync(0xffffffffu, se,  off);
        const float sev2 = __shfl_xor_sync(0xffffffffu, sev, off);
        const float mm = fmaxf(m, m2);
        const float c1 = __expf(m  - mm);
        const float c2 = __expf(m2 - mm);
        se  = fmaf(se,  c1, se2  * c2);
        sev = fmaf(sev, c1, sev2 * c2);
        m = mm;
    }

    // group leader publishes its query value; 4th arriver for b combines.
    if (k == 0) {
        g_qv[q] = sev / se;
        __threadfence();                       // release
        const int old = atomicAdd(&g_done[b], 1);
        if (old == 3) {
            __threadfence();                   // acquire
            const float vss0 = g_qv[b * 4 + 0];
            const float ves0 = g_qv[b * 4 + 1];
            const float vss1 = g_qv[b * 4 + 2];
            const float ves1 = g_qv[b * 4 + 3];

            const float* p0 = phi + b * 20;
            const float* p1 = p0 + 10;
            const float pr0 = fmaf(p0[0], w0, fmaf(p0[1], w1, fmaf(p0[2], w2,
                              fmaf(p0[3], w3, fmaf(p0[4], w4, p0[5] * w5)))));
            const float pr1 = fmaf(p1[0], w0, fmaf(p1[1], w1, fmaf(p1[2], w2,
                              fmaf(p1[3], w3, fmaf(p1[4], w4, p1[5] * w5)))));

            const float left_der  = pr0 + (ves0 - vss0);
            const float right_der = pr1 + (ves1 - vss1);
            const float d = left_der - right_der;

            float2 r;
            r.x = 1.0f / (1.0f + expf(-d));
            r.y = 1.0f / (1.0f + expf(d));
            reinterpret_cast<float2*>(out)[b] = r;

            g_done[b] = 0;                     // restore for next graph replay
        }
    }
}

extern "C" void kernel_launch(void* const* d_in, const int* in_sizes, int n_in,
                              void* d_out, int out_size) {
    const float* phi   = (const float*)d_in[0];  // (B, 2, 10)
    const float* w_lin = (const float*)d_in[1];  // (1, 6)
    const float* succ  = (const float*)d_in[2];  // (S, H, W, F)
    float* out = (float*)d_out;                  // (B, 2, 1)

    k_hist<<<NQ / 1024, 1024>>>(phi);
    k_scan<<<1, 1024>>>();
    k_scatter<<<NQ / 1024, 1024>>>();
    k_main<<<NQ / 16, 128>>>(phi, w_lin, succ, out);
}